// round 1
// baseline (speedup 1.0000x reference)
#include <cuda_runtime.h>

// Problem constants
#define N_TOK 400
#define NR    399     // fencepost rows = N_TOK - 1
#define DD    1024    // input dim
#define RR    1024    // repr dim
#define LL    112     // labels
#define HALF  512

// Scratch: u[j,r] = fp[j] . W[r,:]   and  ub = u + b  (each 1.63 MB, L2-resident)
__device__ float g_u [NR * RR];
__device__ float g_ub[NR * RR];

// Accurate-enough tanh: e^{2x} via MUFU.EX2, then (t-1)/(t+1) via MUFU.RCP.
// Abs error ~1e-7 (EX2/RCP are ~2^-22 rel; cancellation near 0 bounded by ulp(1)).
__device__ __forceinline__ float fast_tanh(float x) {
    float xc = fminf(fmaxf(x, -20.0f), 20.0f);
    float t;
    asm("ex2.approx.f32 %0, %1;" : "=f"(t) : "f"(xc * 2.8853900817779268f)); // 2*log2(e)
    float num = t - 1.0f;
    float den = t + 1.0f;
    float r;
    asm("rcp.approx.f32 %0, %1;" : "=f"(r) : "f"(den));
    return num * r;
}

// ---------------------------------------------------------------------------
// Kernel A: u[j,r] = sum_d fp[j,d] * W[r,d];  ub = u + b
// fp[j,d] = (d < 512) ? x[j,d] : -x[j+1,d]
// Tiled GEMM: 64(j) x 64(r) per block, BK=16, 256 threads, 4x4 microtile.
// ---------------------------------------------------------------------------
__global__ void compute_u_kernel(const float* __restrict__ x,
                                 const float* __restrict__ W,
                                 const float* __restrict__ b) {
    __shared__ float As[16][68];   // [k][m]  (fp tile, transposed)
    __shared__ float Bs[16][68];   // [k][n]  (W tile, transposed)

    const int tid = threadIdx.x;
    const int j0 = blockIdx.x * 64;
    const int r0 = blockIdx.y * 64;
    const int tx = tid & 15;    // n-direction group (r)
    const int ty = tid >> 4;    // m-direction group (j)

    float acc[4][4] = {};

    const int lk = tid & 15;          // col within K-chunk
    const int lrow = tid >> 4;        // 0..15 (+e*16)

    for (int kc = 0; kc < DD; kc += 16) {
        __syncthreads();
        #pragma unroll
        for (int e = 0; e < 4; e++) {
            int m = lrow + e * 16;
            int d = kc + lk;
            // fp tile
            float v = 0.0f;
            int j = j0 + m;
            if (j < NR) {
                v = (d < HALF) ? x[j * DD + d] : -x[(j + 1) * DD + d];
            }
            As[lk][m] = v;
            // W tile (r dimension is exactly 1024, no guard needed)
            Bs[lk][m] = W[(r0 + m) * DD + d];
        }
        __syncthreads();
        #pragma unroll
        for (int k = 0; k < 16; k++) {
            float a0 = As[k][ty * 4 + 0];
            float a1 = As[k][ty * 4 + 1];
            float a2 = As[k][ty * 4 + 2];
            float a3 = As[k][ty * 4 + 3];
            float b0 = Bs[k][tx * 4 + 0];
            float b1 = Bs[k][tx * 4 + 1];
            float b2 = Bs[k][tx * 4 + 2];
            float b3 = Bs[k][tx * 4 + 3];
            acc[0][0] += a0 * b0; acc[0][1] += a0 * b1; acc[0][2] += a0 * b2; acc[0][3] += a0 * b3;
            acc[1][0] += a1 * b0; acc[1][1] += a1 * b1; acc[1][2] += a1 * b2; acc[1][3] += a1 * b3;
            acc[2][0] += a2 * b0; acc[2][1] += a2 * b1; acc[2][2] += a2 * b2; acc[2][3] += a2 * b3;
            acc[3][0] += a3 * b0; acc[3][1] += a3 * b1; acc[3][2] += a3 * b2; acc[3][3] += a3 * b3;
        }
    }

    #pragma unroll
    for (int i = 0; i < 4; i++) {
        int j = j0 + ty * 4 + i;
        if (j < NR) {
            #pragma unroll
            for (int n = 0; n < 4; n++) {
                int r = r0 + tx * 4 + n;
                float v = acc[i][n];
                g_u [j * RR + r] = v;
                g_ub[j * RR + r] = v + b[r];
            }
        }
    }
}

// ---------------------------------------------------------------------------
// Kernel B: out[i,j,l] = sum_r tanh(ub[j,r] - u[i,r]) * P[r,l] + out_bias[l]
// Per block: 8 i x 8 j = 64 pairs, all 112 labels, K-chunks of 32.
// 256 threads: thread = (pg 0..15, lg 0..15), owns 4 pairs x 7 labels = 28 acc.
// ---------------------------------------------------------------------------
#define TI 8
#define TJ 8
#define KC 32

__global__ void pair_kernel(const float* __restrict__ P,
                            const float* __restrict__ ob,
                            float* __restrict__ out) {
    __shared__ float su [TI][KC];
    __shared__ float sub[TJ][KC];
    __shared__ float sh [TI * TJ][KC + 1];   // [pair][k], padded
    __shared__ float sP [KC][LL];            // [k][l]

    const int tid = threadIdx.x;
    const int i0 = blockIdx.x * TI;
    const int j0 = blockIdx.y * TJ;
    const int pg = tid & 15;    // pair group -> pairs pg*4 .. pg*4+3
    const int lg = tid >> 4;    // label group -> labels lg*7 .. lg*7+6
    const int p0 = pg * 4;
    const int l0 = lg * 7;

    float acc[4][7] = {};

    for (int kc = 0; kc < RR; kc += KC) {
        __syncthreads();
        // load u / ub row chunks (TI*KC = 256 elems each; one per thread)
        {
            int ii = tid >> 5;       // 0..7
            int k  = tid & 31;
            int ig = i0 + ii;
            int jg = j0 + ii;
            su [ii][k] = (ig < NR) ? g_u [ig * RR + kc + k] : 0.0f;
            sub[ii][k] = (jg < NR) ? g_ub[jg * RR + kc + k] : 0.0f;
        }
        // load P chunk: 32x112 = 3584 elems, 14 per thread, coalesced
        #pragma unroll
        for (int e = 0; e < 14; e++) {
            int idx = tid + e * 256;
            int k = idx / LL;
            int l = idx - k * LL;
            sP[k][l] = P[(kc + k) * LL + l];
        }
        __syncthreads();
        // compute h tile: 64 pairs x 32 k = 2048 vals, 8 per thread
        #pragma unroll
        for (int e = 0; e < 8; e++) {
            int idx = tid + e * 256;
            int p = idx >> 5;
            int k = idx & 31;
            int ii = p >> 3;
            int jj = p & 7;
            sh[p][k] = fast_tanh(sub[jj][k] - su[ii][k]);
        }
        __syncthreads();
        // accumulate: 28 FFMA per k per thread
        #pragma unroll
        for (int k = 0; k < KC; k++) {
            float h0 = sh[p0 + 0][k];
            float h1 = sh[p0 + 1][k];
            float h2 = sh[p0 + 2][k];
            float h3 = sh[p0 + 3][k];
            #pragma unroll
            for (int l = 0; l < 7; l++) {
                float pv = sP[k][l0 + l];
                acc[0][l] += h0 * pv;
                acc[1][l] += h1 * pv;
                acc[2][l] += h2 * pv;
                acc[3][l] += h3 * pv;
            }
        }
    }

    // epilogue
    float obv[7];
    #pragma unroll
    for (int l = 0; l < 7; l++) obv[l] = ob[l0 + l];

    #pragma unroll
    for (int e = 0; e < 4; e++) {
        int p = p0 + e;
        int ii = p >> 3;
        int jj = p & 7;
        int ig = i0 + ii;
        int jg = j0 + jj;
        if (ig < NR && jg < NR) {
            size_t base = ((size_t)ig * NR + jg) * LL + l0;
            #pragma unroll
            for (int l = 0; l < 7; l++) {
                out[base + l] = acc[e][l] + obv[l];
            }
        }
    }
}

// ---------------------------------------------------------------------------
// Launch. Inputs (metadata order): x(400x1024), W(1024x1024), b(1024),
// P(1024x112), out_bias(1x112). Output: (399,399,112) f32.
// ---------------------------------------------------------------------------
extern "C" void kernel_launch(void* const* d_in, const int* in_sizes, int n_in,
                              void* d_out, int out_size) {
    const float* x  = (const float*)d_in[0];
    const float* W  = (const float*)d_in[1];
    const float* b  = (const float*)d_in[2];
    const float* P  = (const float*)d_in[3];
    const float* ob = (const float*)d_in[4];
    float* out = (float*)d_out;

    dim3 gridA((NR + 63) / 64, RR / 64);       // 7 x 16
    compute_u_kernel<<<gridA, 256>>>(x, W, b);

    dim3 gridB((NR + TI - 1) / TI, (NR + TJ - 1) / TJ);  // 50 x 50
    pair_kernel<<<gridB, 256>>>(P, ob, out);
}

// round 5
// speedup vs baseline: 3.6822x; 3.6822x over previous
#include <cuda_runtime.h>
#include <cuda_bf16.h>
#include <cstdint>

#define NR   399
#define DD   1024
#define RR   1024
#define LL   112
#define HALF 512

// Precomputed tables
__device__ float g_u [NR * RR];            // u[j,r] = fp[j] . W[r,:]
__device__ float g_ub[NR * RR];            // u + b
__device__ __nv_bfloat16 g_ph[LL * RR];    // P transposed [l][r], hi bf16
__device__ __nv_bfloat16 g_pl[LL * RR];    // residual lo bf16

// ---------------------------------------------------------------------------
// Direct tanh via MUFU: t = 2^(x*2*log2(e)); (t-1)/(t+1). ~1e-7 abs err.
// No clamp needed: |x| <= ~12 here, ex2 cannot overflow.
// ---------------------------------------------------------------------------
__device__ __forceinline__ float tanh_dir(float x) {
    float t;
    asm("ex2.approx.f32 %0, %1;" : "=f"(t) : "f"(x * 2.8853900817779268f));
    float r;
    asm("rcp.approx.f32 %0, %1;" : "=f"(r) : "f"(t + 1.0f));
    return (t - 1.0f) * r;
}

__device__ __forceinline__ void mma_bf16(float* d, const uint32_t* a,
                                         uint32_t b0, uint32_t b1) {
    asm volatile(
        "mma.sync.aligned.m16n8k16.row.col.f32.bf16.bf16.f32 "
        "{%0,%1,%2,%3}, {%4,%5,%6,%7}, {%8,%9}, {%0,%1,%2,%3};\n"
        : "+f"(d[0]), "+f"(d[1]), "+f"(d[2]), "+f"(d[3])
        : "r"(a[0]), "r"(a[1]), "r"(a[2]), "r"(a[3]), "r"(b0), "r"(b1));
}

// ---------------------------------------------------------------------------
// Kernel A: u = fp @ W^T ; store u and u+b.  Tile 32(j) x 64(r), 128 thr.
// ---------------------------------------------------------------------------
__global__ void compute_u_kernel(const float* __restrict__ x,
                                 const float* __restrict__ W,
                                 const float* __restrict__ b) {
    __shared__ float As[16][36];
    __shared__ float Bs[16][68];

    const int tid = threadIdx.x;
    const int j0 = blockIdx.x * 32;
    const int r0 = blockIdx.y * 64;
    const int tx = tid & 15;
    const int ty = tid >> 4;

    float acc[4][4] = {};

    for (int kc = 0; kc < DD; kc += 16) {
        __syncthreads();
        #pragma unroll
        for (int e = 0; e < 4; e++) {
            int idx = tid + e * 128;
            int k = idx & 15, m = idx >> 4;
            int j = j0 + m, d = kc + k;
            float v = 0.0f;
            if (j < NR) v = (d < HALF) ? x[j * DD + d] : -x[(j + 1) * DD + d];
            As[k][m] = v;
        }
        #pragma unroll
        for (int e = 0; e < 8; e++) {
            int idx = tid + e * 128;
            int k = idx & 15, n = idx >> 4;
            Bs[k][n] = W[(r0 + n) * DD + kc + k];
        }
        __syncthreads();
        #pragma unroll
        for (int k = 0; k < 16; k++) {
            float a0 = As[k][ty*4+0], a1 = As[k][ty*4+1], a2 = As[k][ty*4+2], a3 = As[k][ty*4+3];
            float b0 = Bs[k][tx*4+0], b1 = Bs[k][tx*4+1], b2 = Bs[k][tx*4+2], b3 = Bs[k][tx*4+3];
            acc[0][0] += a0*b0; acc[0][1] += a0*b1; acc[0][2] += a0*b2; acc[0][3] += a0*b3;
            acc[1][0] += a1*b0; acc[1][1] += a1*b1; acc[1][2] += a1*b2; acc[1][3] += a1*b3;
            acc[2][0] += a2*b0; acc[2][1] += a2*b1; acc[2][2] += a2*b2; acc[2][3] += a2*b3;
            acc[3][0] += a3*b0; acc[3][1] += a3*b1; acc[3][2] += a3*b2; acc[3][3] += a3*b3;
        }
    }

    #pragma unroll
    for (int i = 0; i < 4; i++) {
        int j = j0 + ty * 4 + i;
        if (j < NR) {
            #pragma unroll
            for (int n = 0; n < 4; n++) {
                int r = r0 + tx * 4 + n;
                float v = acc[i][n];
                g_u [j * RR + r] = v;
                g_ub[j * RR + r] = v + __ldg(&b[r]);
            }
        }
    }
}

// ---------------------------------------------------------------------------
// Kernel P-split: g_ph[l][r] = bf16(P[r][l]), g_pl = residual
// ---------------------------------------------------------------------------
__global__ void psplit_kernel(const float* __restrict__ P) {
    int idx = blockIdx.x * 256 + threadIdx.x;
    if (idx < LL * RR) {
        int l = idx >> 10;
        int r = idx & 1023;
        float v = P[r * LL + l];
        __nv_bfloat16 h = __float2bfloat16(v);
        g_ph[idx] = h;
        g_pl[idx] = __float2bfloat16(v - __bfloat162float(h));
    }
}

// ---------------------------------------------------------------------------
// Kernel B: HMMA pair GEMM.
// Block: 8 i x 16 j = 128 pairs (M) x 112 labels (N), K=1024 in chunks of 32.
// 8 warps = 4(M: 32 rows each) x 2(N: 56 cols each). 3 bf16 products.
// ---------------------------------------------------------------------------
#define KC 32
#define SA 34   // f32 stride, u/ub staging (conflict-free LDS.64 across 16 rows)
#define SH 36   // half stride, A (h) tiles
#define SB 40   // half stride, B (P) tiles

__global__ void __launch_bounds__(256, 2)
pair_hmma_kernel(const float* __restrict__ ob, float* __restrict__ out) {
    __shared__ float sta[16 * SA];                 // ub rows (j)
    __shared__ float stb[8 * SA];                  // u rows (i)
    __shared__ __nv_bfloat16 Ah[128 * SH];         // h hi
    __shared__ __nv_bfloat16 Al[128 * SH];         // h lo
    __shared__ __nv_bfloat16 Bh[LL * SB];          // P hi
    __shared__ __nv_bfloat16 Bl[LL * SB];          // P lo

    const int tid = threadIdx.x;
    const int wid = tid >> 5;
    const int lane = tid & 31;
    const int g  = lane >> 2;       // 0..7
    const int tg = lane & 3;        // 0..3
    const int i0 = blockIdx.x * 8;
    const int j0 = blockIdx.y * 16;

    const int mw = wid & 3;         // M warp: rows mw*32 .. +31
    const int nw = wid >> 2;        // N warp: cols nw*56 .. +55
    const int mbase = mw * 32;
    const int nbase = nw * 56;

    // h-gen mapping: thread -> (pair hp, k half hk0)
    const int hp  = tid & 127;
    const int hk0 = (tid >> 7) * 16;
    const int hjj = hp & 15;
    const int hii = hp >> 4;

    float acc[2][7][4] = {};

    #pragma unroll 1
    for (int c = 0; c < RR / KC; c++) {
        const int kc = c * KC;
        __syncthreads();

        // stage ub (16 j rows) / u (8 i rows): float2 per thread
        {
            int row = tid >> 4, q = tid & 15;
            int j = j0 + row; if (j > NR - 1) j = NR - 1;
            *(float2*)&sta[row * SA + q * 2] =
                *(const float2*)&g_ub[(size_t)j * RR + kc + q * 2];
            if (tid < 128) {
                int i = i0 + row; if (i > NR - 1) i = NR - 1;
                *(float2*)&stb[row * SA + q * 2] =
                    *(const float2*)&g_u[(size_t)i * RR + kc + q * 2];
            }
        }
        // stage P hi/lo chunk: 112 rows x 32 halves, uint4 per 8 halves
        #pragma unroll
        for (int e = 0; e < 2; e++) {
            int idx = tid + e * 256;
            if (idx < 448) {
                int rp = idx >> 2, sg = idx & 3;
                *(uint4*)&Bh[rp * SB + sg * 8] =
                    *(const uint4*)&g_ph[rp * RR + kc + sg * 8];
                *(uint4*)&Bl[rp * SB + sg * 8] =
                    *(const uint4*)&g_pl[rp * RR + kc + sg * 8];
            }
        }
        __syncthreads();

        // h-gen: thread computes 16 k values of h for pair hp; split to bf16 hi/lo
        {
            const float* ap = &sta[hjj * SA + hk0];
            const float* bp = &stb[hii * SA + hk0];
            #pragma unroll
            for (int kk = 0; kk < 16; kk += 2) {
                float2 av = *(const float2*)&ap[kk];
                float2 bv = *(const float2*)&bp[kk];
                float h0 = tanh_dir(av.x - bv.x);
                float h1 = tanh_dir(av.y - bv.y);
                uint32_t hpk;
                asm("cvt.rn.bf16x2.f32 %0, %1, %2;" : "=r"(hpk) : "f"(h1), "f"(h0));
                float r0 = h0 - __uint_as_float(hpk << 16);
                float r1 = h1 - __uint_as_float(hpk & 0xFFFF0000u);
                uint32_t lpk;
                asm("cvt.rn.bf16x2.f32 %0, %1, %2;" : "=r"(lpk) : "f"(r1), "f"(r0));
                *(uint32_t*)&Ah[hp * SH + hk0 + kk] = hpk;
                *(uint32_t*)&Al[hp * SH + hk0 + kk] = lpk;
            }
        }
        __syncthreads();

        // HMMA: 2 k-steps x 2 m-frags x 7 n-frags x 3 products
        #pragma unroll
        for (int ks = 0; ks < KC; ks += 16) {
            uint32_t ah[2][4], al[2][4];
            #pragma unroll
            for (int mf = 0; mf < 2; mf++) {
                int m0 = mbase + mf * 16;
                ah[mf][0] = *(const uint32_t*)&Ah[(m0 + g)     * SH + ks + tg * 2];
                ah[mf][1] = *(const uint32_t*)&Ah[(m0 + g + 8) * SH + ks + tg * 2];
                ah[mf][2] = *(const uint32_t*)&Ah[(m0 + g)     * SH + ks + tg * 2 + 8];
                ah[mf][3] = *(const uint32_t*)&Ah[(m0 + g + 8) * SH + ks + tg * 2 + 8];
                al[mf][0] = *(const uint32_t*)&Al[(m0 + g)     * SH + ks + tg * 2];
                al[mf][1] = *(const uint32_t*)&Al[(m0 + g + 8) * SH + ks + tg * 2];
                al[mf][2] = *(const uint32_t*)&Al[(m0 + g)     * SH + ks + tg * 2 + 8];
                al[mf][3] = *(const uint32_t*)&Al[(m0 + g + 8) * SH + ks + tg * 2 + 8];
            }
            #pragma unroll
            for (int nf = 0; nf < 7; nf++) {
                int n = nbase + nf * 8 + g;
                uint32_t bh0 = *(const uint32_t*)&Bh[n * SB + ks + tg * 2];
                uint32_t bh1 = *(const uint32_t*)&Bh[n * SB + ks + tg * 2 + 8];
                uint32_t bl0 = *(const uint32_t*)&Bl[n * SB + ks + tg * 2];
                uint32_t bl1 = *(const uint32_t*)&Bl[n * SB + ks + tg * 2 + 8];
                #pragma unroll
                for (int mf = 0; mf < 2; mf++) {
                    mma_bf16(acc[mf][nf], ah[mf], bh0, bh1);
                    mma_bf16(acc[mf][nf], al[mf], bh0, bh1);
                    mma_bf16(acc[mf][nf], ah[mf], bl0, bl1);
                }
            }
        }
    }

    // epilogue: d frag (mf,nf): rows p = mbase+mf*16+g (+8), cols l = nbase+nf*8+tg*2 (+1)
    #pragma unroll
    for (int mf = 0; mf < 2; mf++) {
        const int ii = (mbase >> 4) + mf;        // fixed i-row for this warp/mf
        const int i = i0 + ii;
        const bool iok = (i < NR);
        const int jA = j0 + g;                   // rows g
        const int jB = j0 + g + 8;               // rows g+8
        const bool jAok = iok && (jA < NR);
        const bool jBok = iok && (jB < NR);
        float* rowA = out + ((size_t)i * NR + jA) * LL;
        float* rowB = out + ((size_t)i * NR + jB) * LL;
        #pragma unroll
        for (int nf = 0; nf < 7; nf++) {
            int l = nbase + nf * 8 + tg * 2;
            float b0 = __ldg(&ob[l]);
            float b1 = __ldg(&ob[l + 1]);
            if (jAok) {
                float2 v = { acc[mf][nf][0] + b0, acc[mf][nf][1] + b1 };
                *(float2*)&rowA[l] = v;
            }
            if (jBok) {
                float2 v = { acc[mf][nf][2] + b0, acc[mf][nf][3] + b1 };
                *(float2*)&rowB[l] = v;
            }
        }
    }
}

// ---------------------------------------------------------------------------
// Launch. Inputs: x(400x1024), W(1024x1024), b(1024), P(1024x112), out_bias(112)
// ---------------------------------------------------------------------------
extern "C" void kernel_launch(void* const* d_in, const int* in_sizes, int n_in,
                              void* d_out, int out_size) {
    const float* x  = (const float*)d_in[0];
    const float* W  = (const float*)d_in[1];
    const float* b  = (const float*)d_in[2];
    const float* P  = (const float*)d_in[3];
    const float* ob = (const float*)d_in[4];
    float* out = (float*)d_out;

    compute_u_kernel<<<dim3(13, 16), 128>>>(x, W, b);
    psplit_kernel<<<(LL * RR + 255) / 256, 256>>>(P);
    pair_hmma_kernel<<<dim3(50, 25), 256>>>(ob, out);
}

// round 8
// speedup vs baseline: 4.0284x; 1.0940x over previous
#include <cuda_runtime.h>
#include <cuda_bf16.h>
#include <cstdint>

#define NR   399
#define DD   1024
#define RR   1024
#define LL   112
#define HALF 512

// Precomputed tables
__device__ float g_u [NR * RR];            // u[j,r] = fp[j] . W[r,:]
__device__ float g_ub[NR * RR];            // u + b
__device__ __nv_bfloat16 g_ph[LL * RR];    // P transposed [l][r], hi bf16
__device__ __nv_bfloat16 g_pl[LL * RR];    // residual lo bf16

// ---------------------------------------------------------------------------
// Direct tanh via MUFU: t = 2^(x*2*log2(e)); (t-1)/(t+1). ~1e-7 abs err.
// ---------------------------------------------------------------------------
__device__ __forceinline__ float tanh_dir(float x) {
    float t;
    asm("ex2.approx.f32 %0, %1;" : "=f"(t) : "f"(x * 2.8853900817779268f));
    float r;
    asm("rcp.approx.f32 %0, %1;" : "=f"(r) : "f"(t + 1.0f));
    return (t - 1.0f) * r;
}

__device__ __forceinline__ void mma_bf16(float* d, const uint32_t* a,
                                         uint32_t b0, uint32_t b1) {
    asm volatile(
        "mma.sync.aligned.m16n8k16.row.col.f32.bf16.bf16.f32 "
        "{%0,%1,%2,%3}, {%4,%5,%6,%7}, {%8,%9}, {%0,%1,%2,%3};\n"
        : "+f"(d[0]), "+f"(d[1]), "+f"(d[2]), "+f"(d[3])
        : "r"(a[0]), "r"(a[1]), "r"(a[2]), "r"(a[3]), "r"(b0), "r"(b1));
}

// ---------------------------------------------------------------------------
// Kernel A v2: u = fp @ W^T ; store u and u+b.
// Tile 32(j) x 64(r), BK=32, 128 threads, 4x4 microtile.
// [k][*] smem layouts -> LDS.128 fragment loads. Register-staged double buffer.
// Fencepost sign/row-shift uniform per 32-chunk (512 % 32 == 0).
// ---------------------------------------------------------------------------
#define SAW 36
#define SBW 68

__global__ void __launch_bounds__(128, 4)
compute_u_kernel(const float* __restrict__ x,
                 const float* __restrict__ W,
                 const float* __restrict__ b) {
    __shared__ float As[32][SAW];   // [k][m]
    __shared__ float Bs[32][SBW];   // [k][n]

    const int tid = threadIdx.x;
    const int j0 = blockIdx.x * 32;
    const int r0 = blockIdx.y * 64;

    // A staging map: row m = tid&31 (j), kb = tid>>5 (k-octet 0..3)
    const int am = tid & 31;
    const int akb = (tid >> 5) * 8;
    int jj = j0 + am; if (jj > NR - 1) jj = NR - 1;

    // B staging map: n = tid&63, kh = tid>>6 (k-hex 0..1)
    const int bn = tid & 63;
    const int bkh = (tid >> 6) * 16;

    // compute map: 4x4 microtile
    const int m0 = (tid >> 4) * 4;   // j dir
    const int n0 = (tid & 15) * 4;   // r dir

    float ar[8], br[16];
    float acc[4][4] = {};

    // prologue: load chunk 0 (kc=0 < HALF: +x[jj])
    {
        const float* ap = x + (size_t)jj * DD + akb;
        *(float4*)&ar[0] = *(const float4*)&ap[0];
        *(float4*)&ar[4] = *(const float4*)&ap[4];
        const float* bp = W + (size_t)(r0 + bn) * DD + bkh;
        #pragma unroll
        for (int q = 0; q < 4; q++)
            *(float4*)&br[q * 4] = *(const float4*)&bp[q * 4];
    }

    #pragma unroll 1
    for (int c = 0; c < DD / 32; c++) {
        __syncthreads();
        #pragma unroll
        for (int q = 0; q < 8; q++) As[akb + q][am] = ar[q];
        #pragma unroll
        for (int q = 0; q < 16; q++) Bs[bkh + q][bn] = br[q];
        __syncthreads();

        if (c < DD / 32 - 1) {
            const int kc = (c + 1) * 32;
            const int neg = (kc >= HALF);
            const float* ap = x + (size_t)(jj + neg) * DD + kc + akb;
            *(float4*)&ar[0] = *(const float4*)&ap[0];
            *(float4*)&ar[4] = *(const float4*)&ap[4];
            if (neg) {
                #pragma unroll
                for (int q = 0; q < 8; q++) ar[q] = -ar[q];
            }
            const float* bp = W + (size_t)(r0 + bn) * DD + kc + bkh;
            #pragma unroll
            for (int q = 0; q < 4; q++)
                *(float4*)&br[q * 4] = *(const float4*)&bp[q * 4];
        }

        #pragma unroll 8
        for (int k = 0; k < 32; k++) {
            float4 a4 = *(const float4*)&As[k][m0];
            float4 b4 = *(const float4*)&Bs[k][n0];
            acc[0][0] += a4.x * b4.x; acc[0][1] += a4.x * b4.y;
            acc[0][2] += a4.x * b4.z; acc[0][3] += a4.x * b4.w;
            acc[1][0] += a4.y * b4.x; acc[1][1] += a4.y * b4.y;
            acc[1][2] += a4.y * b4.z; acc[1][3] += a4.y * b4.w;
            acc[2][0] += a4.z * b4.x; acc[2][1] += a4.z * b4.y;
            acc[2][2] += a4.z * b4.z; acc[2][3] += a4.z * b4.w;
            acc[3][0] += a4.w * b4.x; acc[3][1] += a4.w * b4.y;
            acc[3][2] += a4.w * b4.z; acc[3][3] += a4.w * b4.w;
        }
    }

    float bv[4];
    #pragma unroll
    for (int q = 0; q < 4; q++) bv[q] = __ldg(&b[r0 + n0 + q]);

    #pragma unroll
    for (int mi = 0; mi < 4; mi++) {
        int j = j0 + m0 + mi;
        if (j < NR) {
            size_t base = (size_t)j * RR + r0 + n0;
            #pragma unroll
            for (int ni = 0; ni < 4; ni++) {
                float v = acc[mi][ni];
                g_u [base + ni] = v;
                g_ub[base + ni] = v + bv[ni];
            }
        }
    }
}

// ---------------------------------------------------------------------------
// Kernel P-split: g_ph[l][r] = bf16(P[r][l]), g_pl = residual
// ---------------------------------------------------------------------------
__global__ void psplit_kernel(const float* __restrict__ P) {
    int idx = blockIdx.x * 256 + threadIdx.x;
    if (idx < LL * RR) {
        int l = idx >> 10;
        int r = idx & 1023;
        float v = P[r * LL + l];
        __nv_bfloat16 h = __float2bfloat16(v);
        g_ph[idx] = h;
        g_pl[idx] = __float2bfloat16(v - __bfloat162float(h));
    }
}

// ---------------------------------------------------------------------------
// Kernel B: HMMA pair GEMM (unchanged from R5 passing version).
// Block: 8 i x 16 j = 128 pairs (M) x 112 labels (N), K=1024 in chunks of 32.
// 8 warps = 4(M: 32 rows each) x 2(N: 56 cols each). 3 bf16 products.
// ---------------------------------------------------------------------------
#define KC 32
#define SA 34
#define SH 36
#define SB 40

__global__ void __launch_bounds__(256, 2)
pair_hmma_kernel(const float* __restrict__ ob, float* __restrict__ out) {
    __shared__ float sta[16 * SA];
    __shared__ float stb[8 * SA];
    __shared__ __nv_bfloat16 Ah[128 * SH];
    __shared__ __nv_bfloat16 Al[128 * SH];
    __shared__ __nv_bfloat16 Bh[LL * SB];
    __shared__ __nv_bfloat16 Bl[LL * SB];

    const int tid = threadIdx.x;
    const int wid = tid >> 5;
    const int lane = tid & 31;
    const int g  = lane >> 2;
    const int tg = lane & 3;
    const int i0 = blockIdx.x * 8;
    const int j0 = blockIdx.y * 16;

    const int mw = wid & 3;
    const int nw = wid >> 2;
    const int mbase = mw * 32;
    const int nbase = nw * 56;

    const int hp  = tid & 127;
    const int hk0 = (tid >> 7) * 16;
    const int hjj = hp & 15;
    const int hii = hp >> 4;

    float acc[2][7][4] = {};

    #pragma unroll 1
    for (int c = 0; c < RR / KC; c++) {
        const int kc = c * KC;
        __syncthreads();

        {
            int row = tid >> 4, q = tid & 15;
            int j = j0 + row; if (j > NR - 1) j = NR - 1;
            *(float2*)&sta[row * SA + q * 2] =
                *(const float2*)&g_ub[(size_t)j * RR + kc + q * 2];
            if (tid < 128) {
                int i = i0 + row; if (i > NR - 1) i = NR - 1;
                *(float2*)&stb[row * SA + q * 2] =
                    *(const float2*)&g_u[(size_t)i * RR + kc + q * 2];
            }
        }
        #pragma unroll
        for (int e = 0; e < 2; e++) {
            int idx = tid + e * 256;
            if (idx < 448) {
                int rp = idx >> 2, sg = idx & 3;
                *(uint4*)&Bh[rp * SB + sg * 8] =
                    *(const uint4*)&g_ph[rp * RR + kc + sg * 8];
                *(uint4*)&Bl[rp * SB + sg * 8] =
                    *(const uint4*)&g_pl[rp * RR + kc + sg * 8];
            }
        }
        __syncthreads();

        {
            const float* ap = &sta[hjj * SA + hk0];
            const float* bp = &stb[hii * SA + hk0];
            #pragma unroll
            for (int kk = 0; kk < 16; kk += 2) {
                float2 av = *(const float2*)&ap[kk];
                float2 bv = *(const float2*)&bp[kk];
                float h0 = tanh_dir(av.x - bv.x);
                float h1 = tanh_dir(av.y - bv.y);
                uint32_t hpk;
                asm("cvt.rn.bf16x2.f32 %0, %1, %2;" : "=r"(hpk) : "f"(h1), "f"(h0));
                float r0 = h0 - __uint_as_float(hpk << 16);
                float r1 = h1 - __uint_as_float(hpk & 0xFFFF0000u);
                uint32_t lpk;
                asm("cvt.rn.bf16x2.f32 %0, %1, %2;" : "=r"(lpk) : "f"(r1), "f"(r0));
                *(uint32_t*)&Ah[hp * SH + hk0 + kk] = hpk;
                *(uint32_t*)&Al[hp * SH + hk0 + kk] = lpk;
            }
        }
        __syncthreads();

        #pragma unroll
        for (int ks = 0; ks < KC; ks += 16) {
            uint32_t ah[2][4], al[2][4];
            #pragma unroll
            for (int mf = 0; mf < 2; mf++) {
                int m0 = mbase + mf * 16;
                ah[mf][0] = *(const uint32_t*)&Ah[(m0 + g)     * SH + ks + tg * 2];
                ah[mf][1] = *(const uint32_t*)&Ah[(m0 + g + 8) * SH + ks + tg * 2];
                ah[mf][2] = *(const uint32_t*)&Ah[(m0 + g)     * SH + ks + tg * 2 + 8];
                ah[mf][3] = *(const uint32_t*)&Ah[(m0 + g + 8) * SH + ks + tg * 2 + 8];
                al[mf][0] = *(const uint32_t*)&Al[(m0 + g)     * SH + ks + tg * 2];
                al[mf][1] = *(const uint32_t*)&Al[(m0 + g + 8) * SH + ks + tg * 2];
                al[mf][2] = *(const uint32_t*)&Al[(m0 + g)     * SH + ks + tg * 2 + 8];
                al[mf][3] = *(const uint32_t*)&Al[(m0 + g + 8) * SH + ks + tg * 2 + 8];
            }
            #pragma unroll
            for (int nf = 0; nf < 7; nf++) {
                int n = nbase + nf * 8 + g;
                uint32_t bh0 = *(const uint32_t*)&Bh[n * SB + ks + tg * 2];
                uint32_t bh1 = *(const uint32_t*)&Bh[n * SB + ks + tg * 2 + 8];
                uint32_t bl0 = *(const uint32_t*)&Bl[n * SB + ks + tg * 2];
                uint32_t bl1 = *(const uint32_t*)&Bl[n * SB + ks + tg * 2 + 8];
                #pragma unroll
                for (int mf = 0; mf < 2; mf++) {
                    mma_bf16(acc[mf][nf], ah[mf], bh0, bh1);
                    mma_bf16(acc[mf][nf], al[mf], bh0, bh1);
                    mma_bf16(acc[mf][nf], ah[mf], bl0, bl1);
                }
            }
        }
    }

    #pragma unroll
    for (int mf = 0; mf < 2; mf++) {
        const int ii = (mbase >> 4) + mf;
        const int i = i0 + ii;
        const bool iok = (i < NR);
        const int jA = j0 + g;
        const int jB = j0 + g + 8;
        const bool jAok = iok && (jA < NR);
        const bool jBok = iok && (jB < NR);
        float* rowA = out + ((size_t)i * NR + jA) * LL;
        float* rowB = out + ((size_t)i * NR + jB) * LL;
        #pragma unroll
        for (int nf = 0; nf < 7; nf++) {
            int l = nbase + nf * 8 + tg * 2;
            float b0 = __ldg(&ob[l]);
            float b1 = __ldg(&ob[l + 1]);
            if (jAok) {
                float2 v = { acc[mf][nf][0] + b0, acc[mf][nf][1] + b1 };
                *(float2*)&rowA[l] = v;
            }
            if (jBok) {
                float2 v = { acc[mf][nf][2] + b0, acc[mf][nf][3] + b1 };
                *(float2*)&rowB[l] = v;
            }
        }
    }
}

// ---------------------------------------------------------------------------
// Launch. Inputs: x(400x1024), W(1024x1024), b(1024), P(1024x112), out_bias(112)
// ---------------------------------------------------------------------------
extern "C" void kernel_launch(void* const* d_in, const int* in_sizes, int n_in,
                              void* d_out, int out_size) {
    const float* x  = (const float*)d_in[0];
    const float* W  = (const float*)d_in[1];
    const float* b  = (const float*)d_in[2];
    const float* P  = (const float*)d_in[3];
    const float* ob = (const float*)d_in[4];
    float* out = (float*)d_out;

    psplit_kernel<<<(LL * RR + 255) / 256, 256>>>(P);
    compute_u_kernel<<<dim3(13, 16), 128>>>(x, W, b);
    pair_hmma_kernel<<<dim3(50, 25), 256>>>(ob, out);
}